// round 3
// baseline (speedup 1.0000x reference)
#include <cuda_runtime.h>
#include <math_constants.h>

// Problem constants
#define Bn 8
#define Np 16384
#define NUM_GROUPS 512
#define GROUP_SIZE 32
#define UPSCALE_K 512
#define R2 0.25f
#define CONTEXT 256

// Output layout (float32, concatenated flattened outputs)
#define OUT_GROUPS  0                       // (8,256,32,4) = 262144
#define OUT_CENTERS 262144                  // (8,256,4)    = 8192
#define OUT_EMB     270336                  // (8,256)      = 2048
#define OUT_PMASK   272384                  // (8,256,32)   = 65536
// total 337920

// Scratch (no allocs allowed)
__device__ float g_centers[Bn * NUM_GROUPS * 4];
__device__ int   g_glen[Bn];

// ---------------------------------------------------------------------------
// FPS: one block per batch, 1024 threads, 16 points/thread.
// x,y in registers; z and running min-dist in shared (conflict-free).
// ---------------------------------------------------------------------------
#define FPS_T 1024
#define NPT   (Np / FPS_T)   // 16

extern __shared__ float fps_smem[];

__global__ __launch_bounds__(FPS_T, 1)
void fps_kernel(const float* __restrict__ points,
                const int* __restrict__ lengths,
                float* __restrict__ out_centers)
{
    float* z_sh = fps_smem;        // Np floats
    float* mind = fps_smem + Np;   // Np floats

    __shared__ float red_v[32];
    __shared__ int   red_i[32];
    __shared__ float s_bx, s_by, s_bz;
    __shared__ int   s_widx;

    const int b    = blockIdx.x;
    const int tid  = threadIdx.x;
    const int lane = tid & 31;
    const int wid  = tid >> 5;
    const int len  = lengths[b];
    const float4* pts = (const float4*)points + (size_t)b * Np;

    if (tid == 0) g_glen[b] = 0;   // zero counter before group kernel runs

    float x[NPT], y[NPT];
#pragma unroll
    for (int i = 0; i < NPT; i++) {
        int p = tid + i * FPS_T;
        float4 v = pts[p];
        x[i] = v.x; y[i] = v.y;
        z_sh[p] = v.z;
        // Invalid points get -1e30: min-update never fires (d>=0), argmax ignores them.
        mind[p] = (p < len) ? 1e10f : -1e30f;
    }

    // Center 0 = point index 0 (random_start_point=False)
    if (tid == 0) {
        float4 v = pts[0];
        s_bx = v.x; s_by = v.y; s_bz = v.z;
        float* gc = &g_centers[(b * NUM_GROUPS) * 4];
        gc[0] = v.x; gc[1] = v.y; gc[2] = v.z; gc[3] = v.w;
        float* oc = out_centers + (size_t)(b * CONTEXT) * 4;
        oc[0] = v.x; oc[1] = v.y; oc[2] = v.z; oc[3] = v.w;
    }
    __syncthreads();

    for (int k = 1; k < NUM_GROUPS; k++) {
        const float bx = s_bx, by = s_by, bz = s_bz;
        float best = -1e30f;
        int   bidx = -1;
#pragma unroll
        for (int i = 0; i < NPT; i++) {
            int p = tid + i * FPS_T;
            float dx = x[i] - bx;
            float dy = y[i] - by;
            float dz = z_sh[p] - bz;
            float d  = dx * dx + dy * dy + dz * dz;
            float od = mind[p];
            float m  = fminf(od, d);
            if (d < od) mind[p] = d;                       // predicated STS
            if (m > best) { best = m; bidx = p; }          // strict > => lowest index wins
        }
        // warp argmax (tie -> lower index, matching jnp.argmax)
#pragma unroll
        for (int off = 16; off; off >>= 1) {
            float ov = __shfl_down_sync(0xffffffffu, best, off);
            int   oi = __shfl_down_sync(0xffffffffu, bidx, off);
            if (ov > best || (ov == best && oi < bidx)) { best = ov; bidx = oi; }
        }
        if (lane == 0) { red_v[wid] = best; red_i[wid] = bidx; }
        __syncthreads();
        if (wid == 0) {
            best = red_v[lane]; bidx = red_i[lane];
#pragma unroll
            for (int off = 16; off; off >>= 1) {
                float ov = __shfl_down_sync(0xffffffffu, best, off);
                int   oi = __shfl_down_sync(0xffffffffu, bidx, off);
                if (ov > best || (ov == best && oi < bidx)) { best = ov; bidx = oi; }
            }
            if (lane == 0) s_widx = bidx;
        }
        __syncthreads();
        const int widx = s_widx;
        // Owner thread broadcasts coords from registers (avoids serial L2 load)
        if (tid == (widx & (FPS_T - 1))) {
            int ii = widx >> 10;
            float ox = 0.f, oy = 0.f;
#pragma unroll
            for (int j = 0; j < NPT; j++) { if (ii == j) { ox = x[j]; oy = y[j]; } }
            float oz = z_sh[widx];
            s_bx = ox; s_by = oy; s_bz = oz;
            // energy channel (not needed by the loop; latency hidden)
            float w = points[((size_t)(b * Np + widx)) * 4 + 3];
            float* gc = &g_centers[(b * NUM_GROUPS + k) * 4];
            gc[0] = ox; gc[1] = oy; gc[2] = oz; gc[3] = w;
            if (k < CONTEXT) {
                float* oc = out_centers + ((size_t)(b * CONTEXT + k)) * 4;
                oc[0] = ox; oc[1] = oy; oc[2] = oz; oc[3] = w;
            }
        }
        __syncthreads();
    }
}

// ---------------------------------------------------------------------------
// Ball query + energy top-k. One block per (group, batch).
// g >= CONTEXT: count-only (feeds group_lengths).
// g <  CONTEXT: ordered compaction of first 512 in-radius, then 32 argmax rounds.
// ---------------------------------------------------------------------------
#define GT 256

__global__ __launch_bounds__(GT, 4)
void group_kernel(const float* __restrict__ points,
                  const int* __restrict__ lengths,
                  float* __restrict__ out)
{
    __shared__ int   cand_idx[UPSCALE_K];
    __shared__ float cand_e[UPSCALE_K];
    __shared__ int   wsum[8];
    __shared__ float rv[8];
    __shared__ int   rp[8];
    __shared__ int   sel[GROUP_SIZE];

    const int g = blockIdx.x, b = blockIdx.y;
    const int tid = threadIdx.x, lane = tid & 31, wid = tid >> 5;
    const int len = lengths[b];
    const float cx = g_centers[(b * NUM_GROUPS + g) * 4 + 0];
    const float cy = g_centers[(b * NUM_GROUPS + g) * 4 + 1];
    const float cz = g_centers[(b * NUM_GROUPS + g) * 4 + 2];
    const float4* pts = (const float4*)points + (size_t)b * Np;

    if (g >= CONTEXT) {
        // Count-only: full flag <=> (#valid in-radius) >= GROUP_SIZE
        int cnt = 0;
        for (int p = tid; p < Np; p += GT) {
            float4 v = pts[p];
            float dx = v.x - cx, dy = v.y - cy, dz = v.z - cz;
            float d = dx * dx + dy * dy + dz * dz;
            if (p < len && d < R2) cnt++;
        }
#pragma unroll
        for (int off = 16; off; off >>= 1) cnt += __shfl_down_sync(0xffffffffu, cnt, off);
        if (lane == 0) wsum[wid] = cnt;
        __syncthreads();
        if (tid == 0) {
            int t = 0;
#pragma unroll
            for (int w = 0; w < 8; w++) t += wsum[w];
            if (t >= GROUP_SIZE) atomicAdd(&g_glen[b], 1);
        }
        return;
    }

    // --- full mode: ordered stream compaction, chunks of 1024 (4 consecutive pts/thread) ---
    int base = 0;
    for (int chunk = 0; chunk < Np / 1024 && base < UPSCALE_K; chunk++) {
        int p0 = chunk * 1024 + tid * 4;
        float4 v[4];
        bool   pr[4];
        int cnt = 0;
#pragma unroll
        for (int i = 0; i < 4; i++) {
            v[i] = pts[p0 + i];
            float dx = v[i].x - cx, dy = v[i].y - cy, dz = v[i].z - cz;
            float d = dx * dx + dy * dy + dz * dz;
            pr[i] = ((p0 + i) < len) && (d < R2);
            cnt += pr[i] ? 1 : 0;
        }
        // warp inclusive scan of per-thread counts
        int inc = cnt;
#pragma unroll
        for (int off = 1; off < 32; off <<= 1) {
            int o = __shfl_up_sync(0xffffffffu, inc, off);
            if (lane >= off) inc += o;
        }
        int excl = inc - cnt;
        if (lane == 31) wsum[wid] = inc;
        __syncthreads();
        int wpre = 0, total = 0;
#pragma unroll
        for (int w = 0; w < 8; w++) { int s = wsum[w]; if (w < wid) wpre += s; total += s; }
        int pos = base + wpre + excl;
#pragma unroll
        for (int i = 0; i < 4; i++) {
            if (pr[i]) {
                if (pos < UPSCALE_K) { cand_idx[pos] = p0 + i; cand_e[pos] = v[i].w; }
                pos++;
            }
        }
        base += total;         // uniform across threads (local replica)
        __syncthreads();       // protect wsum + cand writes for next chunk / selection
    }
    const int M    = min(base, UPSCALE_K);
    const int npts = min(M, GROUP_SIZE);

    // --- top-npts by energy; ties -> lower candidate position (stable top_k) ---
    for (int r = 0; r < npts; r++) {
        float bv = -CUDART_INF_F;
        int   bp = 0x7fffffff;
        for (int pos = tid; pos < M; pos += GT) {
            float vv = cand_e[pos];
            if (vv > bv) { bv = vv; bp = pos; }
        }
#pragma unroll
        for (int off = 16; off; off >>= 1) {
            float ov = __shfl_down_sync(0xffffffffu, bv, off);
            int   op = __shfl_down_sync(0xffffffffu, bp, off);
            if (ov > bv || (ov == bv && op < bp)) { bv = ov; bp = op; }
        }
        if (lane == 0) { rv[wid] = bv; rp[wid] = bp; }
        __syncthreads();
        if (tid == 0) {
            float bb = rv[0]; int pp = rp[0];
#pragma unroll
            for (int w = 1; w < 8; w++) {
                if (rv[w] > bb || (rv[w] == bb && rp[w] < pp)) { bb = rv[w]; pp = rp[w]; }
            }
            sel[r] = pp;
            cand_e[pp] = -CUDART_INF_F;   // remove from further rounds
        }
        __syncthreads();
    }

    // --- outputs (npts >= 1 always: center itself is in its own ball) ---
    if (tid < GROUP_SIZE) {
        int j = tid;
        int srcpos = sel[(j < npts) ? j : 0];   // fill_empty -> first (top-energy) index
        int src = cand_idx[srcpos];
        float4 v = pts[src];
        ((float4*)(out + OUT_GROUPS))[(size_t)(b * CONTEXT + g) * GROUP_SIZE + j] = v;
        out[OUT_PMASK + (size_t)(b * CONTEXT + g) * GROUP_SIZE + j] = (j < npts) ? 1.0f : 0.0f;
    }
    if (tid == 0 && M >= GROUP_SIZE) atomicAdd(&g_glen[b], 1);
}

// ---------------------------------------------------------------------------
// embedding_mask from group_lengths
// ---------------------------------------------------------------------------
__global__ void finalize_kernel(float* __restrict__ out)
{
    int b = blockIdx.x, i = threadIdx.x;
    out[OUT_EMB + b * CONTEXT + i] = (i < g_glen[b]) ? 1.0f : 0.0f;
}

// ---------------------------------------------------------------------------
extern "C" void kernel_launch(void* const* d_in, const int* in_sizes, int n_in,
                              void* d_out, int out_size)
{
    const float* points  = (const float*)d_in[0];
    const int*   lengths = (const int*)d_in[1];
    float*       out     = (float*)d_out;

    cudaFuncSetAttribute(fps_kernel, cudaFuncAttributeMaxDynamicSharedMemorySize,
                         2 * Np * (int)sizeof(float));

    fps_kernel<<<Bn, FPS_T, 2 * Np * sizeof(float)>>>(points, lengths, out + OUT_CENTERS);
    group_kernel<<<dim3(NUM_GROUPS, Bn), GT>>>(points, lengths, out);
    finalize_kernel<<<Bn, CONTEXT>>>(out);
}

// round 6
// speedup vs baseline: 1.0909x; 1.0909x over previous
#include <cuda_runtime.h>
#include <math_constants.h>
#include <cstdint>

// Problem constants
#define Bn 8
#define Np 16384
#define NUM_GROUPS 512
#define GROUP_SIZE 32
#define UPSCALE_K 512
#define R2 0.25f
#define CONTEXT 256

// Output layout (float32, concatenated flattened outputs)
#define OUT_GROUPS  0                       // (8,256,32,4) = 262144
#define OUT_CENTERS 262144                  // (8,256,4)    = 8192
#define OUT_EMB     270336                  // (8,256)      = 2048
#define OUT_PMASK   272384                  // (8,256,32)   = 65536

// Scratch (no allocs allowed)
__device__ float g_centers[Bn * NUM_GROUPS * 4];
__device__ int   g_glen[Bn];

// ---------------------------------------------------------------------------
// helpers
// ---------------------------------------------------------------------------
typedef unsigned long long ull;

__device__ __forceinline__ uint32_t smem_u32(const void* p) {
    uint32_t r;
    asm("{ .reg .u64 t; cvta.to.shared.u64 t, %1; cvt.u32.u64 %0, t; }"
        : "=r"(r) : "l"(p));
    return r;
}
__device__ __forceinline__ ull pk2(float a, float b) {
    ull r; asm("mov.b64 %0, {%1,%2};" : "=l"(r) : "f"(a), "f"(b)); return r;
}
__device__ __forceinline__ void upk2(float& a, float& b, ull v) {
    asm("mov.b64 {%0,%1}, %2;" : "=f"(a), "=f"(b) : "l"(v));
}
__device__ __forceinline__ ull add2(ull a, ull b) {
    ull r; asm("add.rn.f32x2 %0, %1, %2;" : "=l"(r) : "l"(a), "l"(b)); return r;
}
__device__ __forceinline__ ull mul2(ull a, ull b) {
    ull r; asm("mul.rn.f32x2 %0, %1, %2;" : "=l"(r) : "l"(a), "l"(b)); return r;
}
__device__ __forceinline__ ull fma2(ull a, ull b, ull c) {
    ull r; asm("fma.rn.f32x2 %0, %1, %2, %3;" : "=l"(r) : "l"(a), "l"(b), "l"(c)); return r;
}
__device__ __forceinline__ void mbar_wait_par(uint32_t a, uint32_t par) {
    uint32_t done;
    asm volatile(
        "{\n\t.reg .pred p;\n\t"
        "mbarrier.try_wait.parity.acquire.cluster.shared::cta.b64 p, [%1], %2;\n\t"
        "selp.b32 %0, 1, 0, p;\n\t}"
        : "=r"(done) : "r"(a), "r"(par) : "memory");
    while (!done) {
        asm volatile(
            "{\n\t.reg .pred p;\n\t"
            "mbarrier.try_wait.parity.acquire.cluster.shared::cta.b64 p, [%1], %2, 0x989680;\n\t"
            "selp.b32 %0, 1, 0, p;\n\t}"
            : "=r"(done) : "r"(a), "r"(par) : "memory");
    }
}

// ---------------------------------------------------------------------------
// FPS: cluster of 4 CTAs per batch, 1024 threads each, 4 points/thread.
// x,y,z packed in registers (f32x2), mind in registers. Cross-CTA argmax via
// replicated DSMEM slots + mbarrier (no cluster.sync in the loop).
// ---------------------------------------------------------------------------
#define CL    4
#define FPS_T 1024
#define PPC   (Np / CL)       // 4096 points per CTA

__global__ void __launch_bounds__(FPS_T, 1) __cluster_dims__(CL, 1, 1)
fps_kernel(const float* __restrict__ points,
           const int* __restrict__ lengths,
           float* __restrict__ out_centers)
{
    extern __shared__ float sm[];
    float* px = sm;               // PPC floats (coordinate lookup only)
    float* py = sm + PPC;
    float* pz = sm + 2 * PPC;
    float* pe = sm + 3 * PPC;

    __shared__ float red_v[32];
    __shared__ int   red_i[32];
    __shared__ float slots[2][CL][8];   // [parity][rank][val,idx,x,y,z,pad..]
    __shared__ ull   mbar;
    __shared__ float s_c0[4];

    const int b    = blockIdx.y;
    const int rank = blockIdx.x;
    const int tid  = threadIdx.x;
    const int lane = tid & 31;
    const int wid  = tid >> 5;
    const int len  = lengths[b];
    const float4* pts = (const float4*)points + (size_t)b * Np;
    const int gbase = rank * PPC;

    const uint32_t mbar_a = smem_u32(&mbar);

    if (tid == 0) {
        asm volatile("mbarrier.init.shared.b64 [%0], %1;"
                     :: "r"(mbar_a), "r"(CL) : "memory");
        float4 c0 = pts[0];
        s_c0[0] = c0.x; s_c0[1] = c0.y; s_c0[2] = c0.z; s_c0[3] = c0.w;
        if (rank == 0) {
            g_glen[b] = 0;
            float* gc = &g_centers[(b * NUM_GROUPS) * 4];
            gc[0] = c0.x; gc[1] = c0.y; gc[2] = c0.z; gc[3] = c0.w;
            float* oc = out_centers + (size_t)(b * CONTEXT) * 4;
            oc[0] = c0.x; oc[1] = c0.y; oc[2] = c0.z; oc[3] = c0.w;
        }
    }

    // Load this CTA's 4096 points: registers (packed pairs) + smem lookup copies.
    float mind[4];
    float4 v0 = pts[gbase + tid];
    float4 v1 = pts[gbase + tid + FPS_T];
    float4 v2 = pts[gbase + tid + 2 * FPS_T];
    float4 v3 = pts[gbase + tid + 3 * FPS_T];
    px[tid] = v0.x;              py[tid] = v0.y;              pz[tid] = v0.z;              pe[tid] = v0.w;
    px[tid + FPS_T] = v1.x;      py[tid + FPS_T] = v1.y;      pz[tid + FPS_T] = v1.z;      pe[tid + FPS_T] = v1.w;
    px[tid + 2*FPS_T] = v2.x;    py[tid + 2*FPS_T] = v2.y;    pz[tid + 2*FPS_T] = v2.z;    pe[tid + 2*FPS_T] = v2.w;
    px[tid + 3*FPS_T] = v3.x;    py[tid + 3*FPS_T] = v3.y;    pz[tid + 3*FPS_T] = v3.z;    pe[tid + 3*FPS_T] = v3.w;
    mind[0] = (gbase + tid           < len) ? 1e10f : -1e30f;
    mind[1] = (gbase + tid +   FPS_T < len) ? 1e10f : -1e30f;
    mind[2] = (gbase + tid + 2*FPS_T < len) ? 1e10f : -1e30f;
    mind[3] = (gbase + tid + 3*FPS_T < len) ? 1e10f : -1e30f;

    ull xp0 = pk2(v0.x, v1.x), xp1 = pk2(v2.x, v3.x);
    ull yp0 = pk2(v0.y, v1.y), yp1 = pk2(v2.y, v3.y);
    ull zp0 = pk2(v0.z, v1.z), zp1 = pk2(v2.z, v3.z);

    __syncthreads();
    // mbarrier init must be cluster-visible before any remote arrive
    asm volatile("barrier.cluster.arrive.aligned;" ::: "memory");
    asm volatile("barrier.cluster.wait.aligned;" ::: "memory");

    float bx = s_c0[0], by = s_c0[1], bz = s_c0[2];
    const int gidx0 = gbase + tid;

    for (int k = 1; k < NUM_GROUPS; k++) {
        const ull nbx = pk2(-bx, -bx);
        const ull nby = pk2(-by, -by);
        const ull nbz = pk2(-bz, -bz);

        float best = -CUDART_INF_F;
        int   bidx = 0x7fffffff;
        {   // pair 0: points gidx0, gidx0+1024
            ull dx = add2(xp0, nbx), dy = add2(yp0, nby), dz = add2(zp0, nbz);
            ull d = mul2(dx, dx); d = fma2(dy, dy, d); d = fma2(dz, dz, d);
            float d0, d1; upk2(d0, d1, d);
            float m0 = fminf(mind[0], d0); mind[0] = m0;
            float m1 = fminf(mind[1], d1); mind[1] = m1;
            if (m0 > best) { best = m0; bidx = gidx0; }
            if (m1 > best) { best = m1; bidx = gidx0 + FPS_T; }
        }
        {   // pair 1: points gidx0+2048, gidx0+3072
            ull dx = add2(xp1, nbx), dy = add2(yp1, nby), dz = add2(zp1, nbz);
            ull d = mul2(dx, dx); d = fma2(dy, dy, d); d = fma2(dz, dz, d);
            float d0, d1; upk2(d0, d1, d);
            float m2 = fminf(mind[2], d0); mind[2] = m2;
            float m3 = fminf(mind[3], d1); mind[3] = m3;
            if (m2 > best) { best = m2; bidx = gidx0 + 2 * FPS_T; }
            if (m3 > best) { best = m3; bidx = gidx0 + 3 * FPS_T; }
        }
        // warp argmax (tie -> lower global index)
#pragma unroll
        for (int off = 16; off; off >>= 1) {
            float ov = __shfl_down_sync(0xffffffffu, best, off);
            int   oi = __shfl_down_sync(0xffffffffu, bidx, off);
            if (ov > best || (ov == best && oi < bidx)) { best = ov; bidx = oi; }
        }
        if (lane == 0) { red_v[wid] = best; red_i[wid] = bidx; }
        __syncthreads();

        if (wid == 0) {
            best = red_v[lane]; bidx = red_i[lane];
#pragma unroll
            for (int off = 16; off; off >>= 1) {
                float ov = __shfl_down_sync(0xffffffffu, best, off);
                int   oi = __shfl_down_sync(0xffffffffu, bidx, off);
                if (ov > best || (ov == best && oi < bidx)) { best = ov; bidx = oi; }
            }
            if (lane == 0) {
                int li = bidx - gbase;
                if (li < 0 || li >= PPC) li = 0;   // all-invalid CTA guard
                const uint32_t vb = __float_as_uint(best);
                const uint32_t ib = (uint32_t)bidx;
                const uint32_t xb = __float_as_uint(px[li]);
                const uint32_t yb = __float_as_uint(py[li]);
                const uint32_t zb = __float_as_uint(pz[li]);
                const int buf = (k - 1) & 1;
                const uint32_t slot_local = smem_u32(&slots[buf][rank][0]);
#pragma unroll
                for (int r = 0; r < CL; r++) {
                    asm volatile(
                        "{\n\t.reg .b32 ra;\n\t"
                        "mapa.shared::cluster.u32 ra, %0, %1;\n\t"
                        "st.shared::cluster.v4.b32 [ra], {%2,%3,%4,%5};\n\t"
                        "st.shared::cluster.b32 [ra+16], %6;\n\t}"
                        :: "r"(slot_local), "r"(r),
                           "r"(vb), "r"(ib), "r"(xb), "r"(yb), "r"(zb)
                        : "memory");
                }
#pragma unroll
                for (int r = 0; r < CL; r++) {
                    asm volatile(
                        "{\n\t.reg .b32 ra;\n\t"
                        "mapa.shared::cluster.u32 ra, %0, %1;\n\t"
                        "mbarrier.arrive.release.cluster.shared::cluster.b64 _, [ra];\n\t}"
                        :: "r"(mbar_a), "r"(r)
                        : "memory");
                }
            }
        }

        // all threads wait for all 4 CTAs' arrivals, then reduce the 4 slots
        mbar_wait_par(mbar_a, (uint32_t)((k - 1) & 1));
        {
            const int buf = (k - 1) & 1;
            float4 s = *(const float4*)&slots[buf][0][0];
            float  sz = slots[buf][0][4];
            float wv = s.x; int widx = __float_as_int(s.y);
            bx = s.z; by = s.w; bz = sz;
#pragma unroll
            for (int r = 1; r < CL; r++) {
                float4 sr = *(const float4*)&slots[buf][r][0];
                float  zr = slots[buf][r][4];
                int id = __float_as_int(sr.y);
                if (sr.x > wv || (sr.x == wv && id < widx)) {
                    wv = sr.x; widx = id; bx = sr.z; by = sr.w; bz = zr;
                }
            }
            if (tid == 0 && (widx >> 12) == rank) {
                int li = widx & (PPC - 1);
                float w = pe[li];
                float* gc = &g_centers[(b * NUM_GROUPS + k) * 4];
                gc[0] = bx; gc[1] = by; gc[2] = bz; gc[3] = w;
                if (k < CONTEXT) {
                    float* oc = out_centers + ((size_t)(b * CONTEXT + k)) * 4;
                    oc[0] = bx; oc[1] = by; oc[2] = bz; oc[3] = w;
                }
            }
        }
    }

    // safe teardown
    asm volatile("barrier.cluster.arrive.aligned;" ::: "memory");
    asm volatile("barrier.cluster.wait.aligned;" ::: "memory");
}

// ---------------------------------------------------------------------------
// Ball query + energy top-k. One block per (group, batch).  (unchanged)
// ---------------------------------------------------------------------------
#define GT 256

__global__ __launch_bounds__(GT, 4)
void group_kernel(const float* __restrict__ points,
                  const int* __restrict__ lengths,
                  float* __restrict__ out)
{
    __shared__ int   cand_idx[UPSCALE_K];
    __shared__ float cand_e[UPSCALE_K];
    __shared__ int   wsum[8];
    __shared__ float rv[8];
    __shared__ int   rp[8];
    __shared__ int   sel[GROUP_SIZE];

    const int g = blockIdx.x, b = blockIdx.y;
    const int tid = threadIdx.x, lane = tid & 31, wid = tid >> 5;
    const int len = lengths[b];
    const float cx = g_centers[(b * NUM_GROUPS + g) * 4 + 0];
    const float cy = g_centers[(b * NUM_GROUPS + g) * 4 + 1];
    const float cz = g_centers[(b * NUM_GROUPS + g) * 4 + 2];
    const float4* pts = (const float4*)points + (size_t)b * Np;

    if (g >= CONTEXT) {
        int cnt = 0;
        for (int p = tid; p < Np; p += GT) {
            float4 v = pts[p];
            float dx = v.x - cx, dy = v.y - cy, dz = v.z - cz;
            float d = dx * dx + dy * dy + dz * dz;
            if (p < len && d < R2) cnt++;
        }
#pragma unroll
        for (int off = 16; off; off >>= 1) cnt += __shfl_down_sync(0xffffffffu, cnt, off);
        if (lane == 0) wsum[wid] = cnt;
        __syncthreads();
        if (tid == 0) {
            int t = 0;
#pragma unroll
            for (int w = 0; w < 8; w++) t += wsum[w];
            if (t >= GROUP_SIZE) atomicAdd(&g_glen[b], 1);
        }
        return;
    }

    int base = 0;
    for (int chunk = 0; chunk < Np / 1024 && base < UPSCALE_K; chunk++) {
        int p0 = chunk * 1024 + tid * 4;
        float4 v[4];
        bool   pr[4];
        int cnt = 0;
#pragma unroll
        for (int i = 0; i < 4; i++) {
            v[i] = pts[p0 + i];
            float dx = v[i].x - cx, dy = v[i].y - cy, dz = v[i].z - cz;
            float d = dx * dx + dy * dy + dz * dz;
            pr[i] = ((p0 + i) < len) && (d < R2);
            cnt += pr[i] ? 1 : 0;
        }
        int inc = cnt;
#pragma unroll
        for (int off = 1; off < 32; off <<= 1) {
            int o = __shfl_up_sync(0xffffffffu, inc, off);
            if (lane >= off) inc += o;
        }
        int excl = inc - cnt;
        if (lane == 31) wsum[wid] = inc;
        __syncthreads();
        int wpre = 0, total = 0;
#pragma unroll
        for (int w = 0; w < 8; w++) { int s = wsum[w]; if (w < wid) wpre += s; total += s; }
        int pos = base + wpre + excl;
#pragma unroll
        for (int i = 0; i < 4; i++) {
            if (pr[i]) {
                if (pos < UPSCALE_K) { cand_idx[pos] = p0 + i; cand_e[pos] = v[i].w; }
                pos++;
            }
        }
        base += total;
        __syncthreads();
    }
    const int M    = min(base, UPSCALE_K);
    const int npts = min(M, GROUP_SIZE);

    for (int r = 0; r < npts; r++) {
        float bv = -CUDART_INF_F;
        int   bp = 0x7fffffff;
        for (int pos = tid; pos < M; pos += GT) {
            float vv = cand_e[pos];
            if (vv > bv) { bv = vv; bp = pos; }
        }
#pragma unroll
        for (int off = 16; off; off >>= 1) {
            float ov = __shfl_down_sync(0xffffffffu, bv, off);
            int   op = __shfl_down_sync(0xffffffffu, bp, off);
            if (ov > bv || (ov == bv && op < bp)) { bv = ov; bp = op; }
        }
        if (lane == 0) { rv[wid] = bv; rp[wid] = bp; }
        __syncthreads();
        if (tid == 0) {
            float bb = rv[0]; int pp = rp[0];
#pragma unroll
            for (int w = 1; w < 8; w++) {
                if (rv[w] > bb || (rv[w] == bb && rp[w] < pp)) { bb = rv[w]; pp = rp[w]; }
            }
            sel[r] = pp;
            cand_e[pp] = -CUDART_INF_F;
        }
        __syncthreads();
    }

    if (tid < GROUP_SIZE) {
        int j = tid;
        int srcpos = sel[(j < npts) ? j : 0];
        int src = cand_idx[srcpos];
        float4 v = pts[src];
        ((float4*)(out + OUT_GROUPS))[(size_t)(b * CONTEXT + g) * GROUP_SIZE + j] = v;
        out[OUT_PMASK + (size_t)(b * CONTEXT + g) * GROUP_SIZE + j] = (j < npts) ? 1.0f : 0.0f;
    }
    if (tid == 0 && M >= GROUP_SIZE) atomicAdd(&g_glen[b], 1);
}

// ---------------------------------------------------------------------------
__global__ void finalize_kernel(float* __restrict__ out)
{
    int b = blockIdx.x, i = threadIdx.x;
    out[OUT_EMB + b * CONTEXT + i] = (i < g_glen[b]) ? 1.0f : 0.0f;
}

// ---------------------------------------------------------------------------
extern "C" void kernel_launch(void* const* d_in, const int* in_sizes, int n_in,
                              void* d_out, int out_size)
{
    const float* points  = (const float*)d_in[0];
    const int*   lengths = (const int*)d_in[1];
    float*       out     = (float*)d_out;

    cudaFuncSetAttribute(fps_kernel, cudaFuncAttributeMaxDynamicSharedMemorySize,
                         4 * PPC * (int)sizeof(float));

    fps_kernel<<<dim3(CL, Bn), FPS_T, 4 * PPC * sizeof(float)>>>(points, lengths,
                                                                 out + OUT_CENTERS);
    group_kernel<<<dim3(NUM_GROUPS, Bn), GT>>>(points, lengths, out);
    finalize_kernel<<<Bn, CONTEXT>>>(out);
}

// round 10
// speedup vs baseline: 1.2429x; 1.1394x over previous
#include <cuda_runtime.h>
#include <math_constants.h>
#include <cstdint>

// Problem constants
#define Bn 8
#define Np 16384
#define NUM_GROUPS 512
#define GROUP_SIZE 32
#define UPSCALE_K 512
#define R2 0.25f
#define CONTEXT 256

// Output layout (float32, concatenated flattened outputs)
#define OUT_GROUPS  0                       // (8,256,32,4) = 262144
#define OUT_CENTERS 262144                  // (8,256,4)    = 8192
#define OUT_EMB     270336                  // (8,256)      = 2048
#define OUT_PMASK   272384                  // (8,256,32)   = 65536

// Scratch (no allocs allowed)
__device__ float g_centers[Bn * NUM_GROUPS * 4];
__device__ int   g_glen[Bn];

typedef unsigned long long ull;

// ---------------------------------------------------------------------------
// helpers
// ---------------------------------------------------------------------------
__device__ __forceinline__ uint32_t smem_u32(const void* p) {
    uint32_t r;
    asm("{ .reg .u64 t; cvta.to.shared.u64 t, %1; cvt.u32.u64 %0, t; }"
        : "=r"(r) : "l"(p));
    return r;
}
__device__ __forceinline__ ull pk2(float a, float b) {
    ull r; asm("mov.b64 %0, {%1,%2};" : "=l"(r) : "f"(a), "f"(b)); return r;
}
__device__ __forceinline__ void upk2(float& a, float& b, ull v) {
    asm("mov.b64 {%0,%1}, %2;" : "=f"(a), "=f"(b) : "l"(v));
}
__device__ __forceinline__ ull add2(ull a, ull b) {
    ull r; asm("add.rn.f32x2 %0, %1, %2;" : "=l"(r) : "l"(a), "l"(b)); return r;
}
__device__ __forceinline__ ull mul2(ull a, ull b) {
    ull r; asm("mul.rn.f32x2 %0, %1, %2;" : "=l"(r) : "l"(a), "l"(b)); return r;
}
__device__ __forceinline__ ull fma2(ull a, ull b, ull c) {
    ull r; asm("fma.rn.f32x2 %0, %1, %2, %3;" : "=l"(r) : "l"(a), "l"(b), "l"(c)); return r;
}
// Monotone map: f32 -> u32 preserving total order (handles negatives)
__device__ __forceinline__ uint32_t mono(float f) {
    uint32_t u = __float_as_uint(f);
    return u ^ ((uint32_t)((int32_t)u >> 31) | 0x80000000u);
}

// ---------------------------------------------------------------------------
// FPS: cluster of 4 CTAs per batch, 512 threads, 8 points/thread.
// Packed-key argmax: (mono(dist)<<32)|~idx -> u64 max = argmax, tie->low idx.
// Cross-CTA: replicated slots + release-counter, acquire-spin on local word.
// ---------------------------------------------------------------------------
#define CL    4
#define FPS_T 512
#define NPT   8
#define PPC   (Np / CL)       // 4096 points per CTA

__global__ void __launch_bounds__(FPS_T, 1) __cluster_dims__(CL, 1, 1)
fps_kernel(const float* __restrict__ points,
           const int* __restrict__ lengths,
           float* __restrict__ out_centers)
{
    extern __shared__ float4 sxyz[];           // PPC float4 (x,y,z,e) leader lookup

    __shared__ ull  cta_key[2];                // parity double-buffered argmax word
    __shared__ __align__(16) float slots[2][CL][8];  // [par][rank][khi,klo,x,y,z,...]
    __shared__ uint32_t arrive_cnt;            // monotone counter (4 per iteration)
    __shared__ float s_c0[4];

    const int b    = blockIdx.y;
    const int rank = blockIdx.x;
    const int tid  = threadIdx.x;
    const int lane = tid & 31;
    const int len  = lengths[b];
    const float4* pts = (const float4*)points + (size_t)b * Np;
    const int gbase = rank * PPC;
    const int gidx0 = gbase + tid;

    const uint32_t cnt_a = smem_u32(&arrive_cnt);

    if (tid == 0) {
        cta_key[0] = 0ull; cta_key[1] = 0ull;
        arrive_cnt = 0u;
        float4 c0 = pts[0];
        s_c0[0] = c0.x; s_c0[1] = c0.y; s_c0[2] = c0.z; s_c0[3] = c0.w;
        if (rank == 0) {
            g_glen[b] = 0;
            float* gc = &g_centers[(b * NUM_GROUPS) * 4];
            gc[0] = c0.x; gc[1] = c0.y; gc[2] = c0.z; gc[3] = c0.w;
            float* oc = out_centers + (size_t)(b * CONTEXT) * 4;
            oc[0] = c0.x; oc[1] = c0.y; oc[2] = c0.z; oc[3] = c0.w;
        }
    }

    // Load this CTA's 4096 points: registers (f32x2 pairs) + float4 shadow.
    float mind[NPT];
    ull xp[NPT / 2], yp[NPT / 2], zp[NPT / 2];
#pragma unroll
    for (int j = 0; j < NPT / 2; j++) {
        int i0 = 2 * j, i1 = 2 * j + 1;
        float4 a = pts[gbase + tid + i0 * FPS_T];
        float4 c = pts[gbase + tid + i1 * FPS_T];
        sxyz[tid + i0 * FPS_T] = a;
        sxyz[tid + i1 * FPS_T] = c;
        xp[j] = pk2(a.x, c.x); yp[j] = pk2(a.y, c.y); zp[j] = pk2(a.z, c.z);
        mind[i0] = (gbase + tid + i0 * FPS_T < len) ? 1e10f : -1e30f;
        mind[i1] = (gbase + tid + i1 * FPS_T < len) ? 1e10f : -1e30f;
    }

    __syncthreads();
    // smem init must be cluster-visible before any remote write lands
    asm volatile("barrier.cluster.arrive.aligned;" ::: "memory");
    asm volatile("barrier.cluster.wait.aligned;" ::: "memory");

    float bx = s_c0[0], by = s_c0[1], bz = s_c0[2];

    for (int k = 1; k < NUM_GROUPS; k++) {
        const int par = k & 1;
        const ull nbx = pk2(-bx, -bx);
        const ull nby = pk2(-by, -by);
        const ull nbz = pk2(-bz, -bz);

        uint32_t bmono = 0u;    // mono of best (0 = smallest possible)
        uint32_t bnid  = 0u;    // ~idx of best
#pragma unroll
        for (int j = 0; j < NPT / 2; j++) {
            ull dx = add2(xp[j], nbx), dy = add2(yp[j], nby), dz = add2(zp[j], nbz);
            ull d = mul2(dx, dx); d = fma2(dy, dy, d); d = fma2(dz, dz, d);
            float d0, d1; upk2(d0, d1, d);
            float m0 = fminf(mind[2 * j], d0);     mind[2 * j] = m0;
            float m1 = fminf(mind[2 * j + 1], d1); mind[2 * j + 1] = m1;
            uint32_t o0 = mono(m0), o1 = mono(m1);
            // strict > : earlier (lower-index) point wins ties within thread
            if (o0 > bmono) { bmono = o0; bnid = ~(uint32_t)(gidx0 + (2 * j) * FPS_T); }
            if (o1 > bmono) { bmono = o1; bnid = ~(uint32_t)(gidx0 + (2 * j + 1) * FPS_T); }
        }
        // warp argmax via REDUX: max mono, then max ~idx among tied lanes
        uint32_t wmax = __reduce_max_sync(0xffffffffu, bmono);
        uint32_t cand = (bmono == wmax) ? bnid : 0u;
        uint32_t wnid = __reduce_max_sync(0xffffffffu, cand);
        if (lane == 0) atomicMax(&cta_key[par], (((ull)wmax) << 32) | wnid);
        __syncthreads();

        if (tid == 0) {
            ull key = cta_key[par];
            cta_key[par ^ 1] = 0ull;                  // reset other parity (release-ordered below)
            uint32_t idx = ~(uint32_t)key;
            int li = (int)idx - gbase;
            if (li < 0 || li >= PPC) li = 0;          // all-invalid guard
            float4 w = sxyz[li];
            const uint32_t khi = (uint32_t)(key >> 32);
            const uint32_t klo = (uint32_t)key;
            const uint32_t xb = __float_as_uint(w.x);
            const uint32_t yb = __float_as_uint(w.y);
            const uint32_t zb = __float_as_uint(w.z);
            const uint32_t slot_l = smem_u32(&slots[par][rank][0]);
#pragma unroll
            for (int r = 0; r < CL; r++) {
                asm volatile(
                    "{\n\t.reg .b32 ra;\n\t"
                    "mapa.shared::cluster.u32 ra, %0, %1;\n\t"
                    "st.shared::cluster.v4.b32 [ra], {%2,%3,%4,%5};\n\t"
                    "st.shared::cluster.b32 [ra+16], %6;\n\t}"
                    :: "r"(slot_l), "r"(r), "r"(khi), "r"(klo), "r"(xb), "r"(yb), "r"(zb)
                    : "memory");
            }
#pragma unroll
            for (int r = 0; r < CL; r++) {
                asm volatile(
                    "{\n\t.reg .b32 ra;\n\t"
                    "mapa.shared::cluster.u32 ra, %0, %1;\n\t"
                    "red.release.cluster.shared::cluster.add.u32 [ra], %2;\n\t}"
                    :: "r"(cnt_a), "r"(r), "r"(1u)
                    : "memory");
            }
        }

        // spin on local counter until all CL leaders of round k arrived
        {
            const uint32_t thr = (uint32_t)(k << 2);
            uint32_t c;
            do {
                asm volatile("ld.acquire.cluster.shared::cta.u32 %0, [%1];"
                             : "=r"(c) : "r"(cnt_a) : "memory");
            } while (c < thr);
        }

        // select global winner = max packed key over the 4 slots
        {
            float4 a0 = *(const float4*)&slots[par][0][0]; float z0 = slots[par][0][4];
            float4 a1 = *(const float4*)&slots[par][1][0]; float z1 = slots[par][1][4];
            float4 a2 = *(const float4*)&slots[par][2][0]; float z2 = slots[par][2][4];
            float4 a3 = *(const float4*)&slots[par][3][0]; float z3 = slots[par][3][4];
            ull k0 = (((ull)__float_as_uint(a0.x)) << 32) | __float_as_uint(a0.y);
            ull k1 = (((ull)__float_as_uint(a1.x)) << 32) | __float_as_uint(a1.y);
            ull k2 = (((ull)__float_as_uint(a2.x)) << 32) | __float_as_uint(a2.y);
            ull k3 = (((ull)__float_as_uint(a3.x)) << 32) | __float_as_uint(a3.y);
            ull kw = k0; bx = a0.z; by = a0.w; bz = z0;
            if (k1 > kw) { kw = k1; bx = a1.z; by = a1.w; bz = z1; }
            if (k2 > kw) { kw = k2; bx = a2.z; by = a2.w; bz = z2; }
            if (k3 > kw) { kw = k3; bx = a3.z; by = a3.w; bz = z3; }
            if (tid == 0) {
                uint32_t widx = ~(uint32_t)kw;
                if ((int)(widx >> 12) == rank) {
                    float e = sxyz[widx & (PPC - 1)].w;
                    float* gc = &g_centers[(b * NUM_GROUPS + k) * 4];
                    gc[0] = bx; gc[1] = by; gc[2] = bz; gc[3] = e;
                    if (k < CONTEXT) {
                        float* oc = out_centers + ((size_t)(b * CONTEXT + k)) * 4;
                        oc[0] = bx; oc[1] = by; oc[2] = bz; oc[3] = e;
                    }
                }
            }
        }
    }

    // safe teardown (remote writes may target our smem until everyone is done)
    asm volatile("barrier.cluster.arrive.aligned;" ::: "memory");
    asm volatile("barrier.cluster.wait.aligned;" ::: "memory");
}

// ---------------------------------------------------------------------------
// Ball query + energy top-k. One block per (group, batch).  (unchanged)
// ---------------------------------------------------------------------------
#define GT 256

__global__ __launch_bounds__(GT, 4)
void group_kernel(const float* __restrict__ points,
                  const int* __restrict__ lengths,
                  float* __restrict__ out)
{
    __shared__ int   cand_idx[UPSCALE_K];
    __shared__ float cand_e[UPSCALE_K];
    __shared__ int   wsum[8];
    __shared__ float rv[8];
    __shared__ int   rp[8];
    __shared__ int   sel[GROUP_SIZE];

    const int g = blockIdx.x, b = blockIdx.y;
    const int tid = threadIdx.x, lane = tid & 31, wid = tid >> 5;
    const int len = lengths[b];
    const float cx = g_centers[(b * NUM_GROUPS + g) * 4 + 0];
    const float cy = g_centers[(b * NUM_GROUPS + g) * 4 + 1];
    const float cz = g_centers[(b * NUM_GROUPS + g) * 4 + 2];
    const float4* pts = (const float4*)points + (size_t)b * Np;

    if (g >= CONTEXT) {
        int cnt = 0;
        for (int p = tid; p < Np; p += GT) {
            float4 v = pts[p];
            float dx = v.x - cx, dy = v.y - cy, dz = v.z - cz;
            float d = dx * dx + dy * dy + dz * dz;
            if (p < len && d < R2) cnt++;
        }
#pragma unroll
        for (int off = 16; off; off >>= 1) cnt += __shfl_down_sync(0xffffffffu, cnt, off);
        if (lane == 0) wsum[wid] = cnt;
        __syncthreads();
        if (tid == 0) {
            int t = 0;
#pragma unroll
            for (int w = 0; w < 8; w++) t += wsum[w];
            if (t >= GROUP_SIZE) atomicAdd(&g_glen[b], 1);
        }
        return;
    }

    int base = 0;
    for (int chunk = 0; chunk < Np / 1024 && base < UPSCALE_K; chunk++) {
        int p0 = chunk * 1024 + tid * 4;
        float4 v[4];
        bool   pr[4];
        int cnt = 0;
#pragma unroll
        for (int i = 0; i < 4; i++) {
            v[i] = pts[p0 + i];
            float dx = v[i].x - cx, dy = v[i].y - cy, dz = v[i].z - cz;
            float d = dx * dx + dy * dy + dz * dz;
            pr[i] = ((p0 + i) < len) && (d < R2);
            cnt += pr[i] ? 1 : 0;
        }
        int inc = cnt;
#pragma unroll
        for (int off = 1; off < 32; off <<= 1) {
            int o = __shfl_up_sync(0xffffffffu, inc, off);
            if (lane >= off) inc += o;
        }
        int excl = inc - cnt;
        if (lane == 31) wsum[wid] = inc;
        __syncthreads();
        int wpre = 0, total = 0;
#pragma unroll
        for (int w = 0; w < 8; w++) { int s = wsum[w]; if (w < wid) wpre += s; total += s; }
        int pos = base + wpre + excl;
#pragma unroll
        for (int i = 0; i < 4; i++) {
            if (pr[i]) {
                if (pos < UPSCALE_K) { cand_idx[pos] = p0 + i; cand_e[pos] = v[i].w; }
                pos++;
            }
        }
        base += total;
        __syncthreads();
    }
    const int M    = min(base, UPSCALE_K);
    const int npts = min(M, GROUP_SIZE);

    for (int r = 0; r < npts; r++) {
        float bv = -CUDART_INF_F;
        int   bp = 0x7fffffff;
        for (int pos = tid; pos < M; pos += GT) {
            float vv = cand_e[pos];
            if (vv > bv) { bv = vv; bp = pos; }
        }
#pragma unroll
        for (int off = 16; off; off >>= 1) {
            float ov = __shfl_down_sync(0xffffffffu, bv, off);
            int   op = __shfl_down_sync(0xffffffffu, bp, off);
            if (ov > bv || (ov == bv && op < bp)) { bv = ov; bp = op; }
        }
        if (lane == 0) { rv[wid] = bv; rp[wid] = bp; }
        __syncthreads();
        if (tid == 0) {
            float bb = rv[0]; int pp = rp[0];
#pragma unroll
            for (int w = 1; w < 8; w++) {
                if (rv[w] > bb || (rv[w] == bb && rp[w] < pp)) { bb = rv[w]; pp = rp[w]; }
            }
            sel[r] = pp;
            cand_e[pp] = -CUDART_INF_F;
        }
        __syncthreads();
    }

    if (tid < GROUP_SIZE) {
        int j = tid;
        int srcpos = sel[(j < npts) ? j : 0];
        int src = cand_idx[srcpos];
        float4 v = pts[src];
        ((float4*)(out + OUT_GROUPS))[(size_t)(b * CONTEXT + g) * GROUP_SIZE + j] = v;
        out[OUT_PMASK + (size_t)(b * CONTEXT + g) * GROUP_SIZE + j] = (j < npts) ? 1.0f : 0.0f;
    }
    if (tid == 0 && M >= GROUP_SIZE) atomicAdd(&g_glen[b], 1);
}

// ---------------------------------------------------------------------------
__global__ void finalize_kernel(float* __restrict__ out)
{
    int b = blockIdx.x, i = threadIdx.x;
    out[OUT_EMB + b * CONTEXT + i] = (i < g_glen[b]) ? 1.0f : 0.0f;
}

// ---------------------------------------------------------------------------
extern "C" void kernel_launch(void* const* d_in, const int* in_sizes, int n_in,
                              void* d_out, int out_size)
{
    const float* points  = (const float*)d_in[0];
    const int*   lengths = (const int*)d_in[1];
    float*       out     = (float*)d_out;

    cudaFuncSetAttribute(fps_kernel, cudaFuncAttributeMaxDynamicSharedMemorySize,
                         PPC * (int)sizeof(float4));

    fps_kernel<<<dim3(CL, Bn), FPS_T, PPC * sizeof(float4)>>>(points, lengths,
                                                              out + OUT_CENTERS);
    group_kernel<<<dim3(NUM_GROUPS, Bn), GT>>>(points, lengths, out);
    finalize_kernel<<<Bn, CONTEXT>>>(out);
}